// round 12
// baseline (speedup 1.0000x reference)
#include <cuda_runtime.h>
#include <math_constants.h>

#define PLACEHOLDER_TOKEN_ID (-1)

// Scratch (allocation-free rule: __device__ globals).
__device__ int g_accept[4096];
__device__ int g_recovered[4096];
__device__ int g_bonus[1024];

// One CTA per row. Rows [0, T): draft rows (need softmax denom + draft prob +
// masked argmax of exp(x)/q). Rows [T, T+B): bonus rows (argmax of exp(x)/q_bonus).
//
// argmax(softmax(x)/q) == argmax(exp(x)/q): row-constant positive normalization
// is argmax-invariant, so no normalization needed for the argmaxes.
// The accept test needs p = exp(x_d)/sum(exp(x)); |x| <= ~20 here so an
// unshifted fp32 sum is safe.
__global__ void __launch_bounds__(256)
row_kernel(const int* __restrict__ draft_ids,
           const float* __restrict__ logits,
           const float* __restrict__ temps,
           const float* __restrict__ q,
           const float* __restrict__ q_bonus,
           const float* __restrict__ u,
           int B, int K, int V)
{
    const int row = blockIdx.x;
    const int T = B * K;
    const bool is_bonus = (row >= T);
    const int b = is_bonus ? (row - T) : (row / K);

    const float* __restrict__ lrow = logits + (size_t)row * (size_t)V;
    const float* __restrict__ qrow = (is_bonus ? q_bonus : q) + (size_t)b * (size_t)V;
    const float invt = 1.0f / temps[b];
    const int draft = is_bonus ? -1 : draft_ids[row];

    const int tid = threadIdx.x;

    __shared__ float sh_sd;            // exp(x) at the draft token

    float ssum = 0.0f;
    float best = 0.0f;                 // exp(x)/q > 0 always, so 0 is a safe floor
    int   bidx = 0;

    #pragma unroll 4
    for (int v = tid; v < V; v += 256) {
        const float x  = lrow[v] * invt;
        const float s  = __expf(x);            // 1 MUFU per element
        const float qv = qrow[v];
        ssum += s;
        if (v != draft) {
            // s/qv > best  <=>  s > best*qv  (no MUFU on the common path).
            if (s > best * qv) { best = s / qv; bidx = v; }
        } else {
            sh_sd = s;
        }
    }

    __shared__ float sh_sum[256];
    __shared__ float sh_best[256];
    __shared__ int   sh_idx[256];
    sh_sum[tid]  = ssum;
    sh_best[tid] = best;
    sh_idx[tid]  = bidx;
    __syncthreads();

    #pragma unroll
    for (int off = 128; off > 0; off >>= 1) {
        if (tid < off) {
            sh_sum[tid] += sh_sum[tid + off];
            const float ob = sh_best[tid + off];
            const int   oi = sh_idx[tid + off];
            // lowest-index tie-break to match jnp.argmax
            if (ob > sh_best[tid] || (ob == sh_best[tid] && oi < sh_idx[tid])) {
                sh_best[tid] = ob;
                sh_idx[tid]  = oi;
            }
        }
        __syncthreads();
    }

    if (tid == 0) {
        if (is_bonus) {
            g_bonus[b] = sh_idx[0];
        } else {
            const float p = sh_sd / sh_sum[0];
            g_accept[row]    = (p >= u[row]) ? 1 : 0;
            g_recovered[row] = sh_idx[0];
        }
    }
}

// Sequential early-exit semantics per batch row. Output written as FLOAT:
// evidence (rel_err==NaN, and int -1 == 0xFFFFFFFF == fp32 NaN) says the
// harness output dtype is float32.
__global__ void finalize_kernel(const int* __restrict__ draft_ids,
                                float* __restrict__ out, int B, int K)
{
    const int b = blockIdx.x * blockDim.x + threadIdx.x;
    if (b >= B) return;

    int r = K;
    for (int k = 0; k < K; k++) {
        if (r == K && !g_accept[b * K + k]) r = k;
    }

    for (int k = 0; k < K; k++) {
        int val = PLACEHOLDER_TOKEN_ID;
        if (k < r)       val = draft_ids[b * K + k];
        else if (k == r) val = g_recovered[b * K + k];
        out[b * (K + 1) + k] = (float)val;
    }
    out[b * (K + 1) + K] = (float)((r == K) ? g_bonus[b] : PLACEHOLDER_TOKEN_ID);
}

extern "C" void kernel_launch(void* const* d_in, const int* in_sizes, int n_in,
                              void* d_out, int out_size)
{
    // Layout-agnostic identification by size structure.
    // Sizes are {T, (T+B)*V, B, T, B*V, B*V} with B < T < B*V < (T+B)*V.
    //   min            -> temperatures [B]
    //   max            -> logits       [(T+B)*V]
    //   dup small pair -> draft_token_ids [T] (int), then u [T] (float), in index order
    //   dup large pair -> q [B,V], then q_bonus [B,V], in index order
    int li = 0, ti = 0;
    for (int i = 1; i < n_in; i++) {
        if (in_sizes[i] > in_sizes[li]) li = i;
        if (in_sizes[i] < in_sizes[ti]) ti = i;
    }
    int rest[4]; int nr = 0;
    for (int i = 0; i < n_in; i++) {
        if (i != li && i != ti) rest[nr++] = i;
    }
    // stable sort 4 indices by size (ascending), keeping original index order for ties
    for (int a = 0; a < 3; a++) {
        for (int c = 0; c < 3 - a; c++) {
            if (in_sizes[rest[c]] > in_sizes[rest[c + 1]]) {
                int t = rest[c]; rest[c] = rest[c + 1]; rest[c + 1] = t;
            }
        }
    }
    const int di = rest[0];   // draft_token_ids [T]
    const int ui = rest[1];   // u               [T]
    const int qi = rest[2];   // q               [B*V]
    const int qbi = rest[3];  // q_bonus         [B*V]

    const int*   draft   = (const int*)  d_in[di];
    const float* logits  = (const float*)d_in[li];
    const float* temps   = (const float*)d_in[ti];
    const float* u       = (const float*)d_in[ui];
    const float* q       = (const float*)d_in[qi];
    const float* q_bonus = (const float*)d_in[qbi];

    const int B = in_sizes[ti];
    const int T = in_sizes[di];
    const int K = T / B;
    const int V = in_sizes[qi] / B;

    row_kernel<<<T + B, 256>>>(draft, logits, temps, q, q_bonus, u, B, K, V);

    const int fb = 256;
    finalize_kernel<<<(B + fb - 1) / fb, fb>>>(draft, (float*)d_out, B, K);
}

// round 15
// speedup vs baseline: 3.2215x; 3.2215x over previous
#include <cuda_runtime.h>

#define PLACEHOLDER_TOKEN_ID (-1)
#define TPB 256
#define UN  8

// Scratch (allocation-free rule: __device__ globals).
__device__ int g_accept[4096];
__device__ int g_recovered[4096];
__device__ int g_bonus[1024];

__device__ __forceinline__ float ex2(float x) {
    float r;
    asm("ex2.approx.f32 %0, %1;" : "=f"(r) : "f"(x));
    return r;
}

// One CTA per row. Rows [0, T): draft rows. Rows [T, T+B): bonus rows.
// argmax(softmax(l/t)/q) == argmax(exp2(l*c)/q), c = log2(e)/t  (argmax-invariant
// under positive row-constant scaling). Accept test: p = 2^(l_d*c) / sum 2^(l*c).
// Argmax kept as a fraction (bs, bq): update iff s*bq > bs*q — no division,
// no branch-subroutine in the hot loop; draft token masked via q -> +inf
// (inf/NaN comparison semantics make it unselectable; q==0 rows behave like
// the reference's first-inf argmax).
__global__ void __launch_bounds__(TPB)
row_kernel(const int* __restrict__ draft_ids,
           const float* __restrict__ logits,
           const float* __restrict__ temps,
           const float* __restrict__ q,
           const float* __restrict__ q_bonus,
           const float* __restrict__ u,
           int B, int K, int V)
{
    const int row = blockIdx.x;
    const int T = B * K;
    const bool is_bonus = (row >= T);
    const int b = is_bonus ? (row - T) : (row / K);

    const float* __restrict__ lrow = logits + (size_t)row * (size_t)V;
    const float* __restrict__ qrow = (is_bonus ? q_bonus : q) + (size_t)b * (size_t)V;
    const float c = 1.4426950408889634f / temps[b];    // log2(e) / t
    const int draft = is_bonus ? -1 : draft_ids[row];

    const int tid = threadIdx.x;
    const float INF = __int_as_float(0x7f800000);

    float ssum0 = 0.0f, ssum1 = 0.0f;
    float bs = 0.0f, bq = 1.0f;        // best = bs/bq
    int   bi = 0;

    const int STEP  = TPB * UN;              // 2048 elements per chunk
    const int vmain = (V / STEP) * STEP;

    for (int base = 0; base < vmain; base += STEP) {
        float lv[UN], qv[UN];
        // Front-batched independent loads: 16 LDGs in flight per thread chunk.
        #pragma unroll
        for (int j = 0; j < UN; j++) lv[j] = lrow[base + tid + j * TPB];
        #pragma unroll
        for (int j = 0; j < UN; j++) qv[j] = qrow[base + tid + j * TPB];

        #pragma unroll
        for (int j = 0; j < UN; j++) {
            const int   v = base + tid + j * TPB;
            const float s = ex2(lv[j] * c);
            if (j & 1) ssum1 += s; else ssum0 += s;
            const float qm = (v == draft) ? INF : qv[j];
            // bs==0 & qm==inf -> 0*inf=NaN -> compare false -> draft never taken.
            if (s * bq > bs * qm) { bs = s; bq = qm; bi = v; }
        }
    }
    // Scalar tail.
    for (int v = vmain + tid; v < V; v += TPB) {
        const float s = ex2(lrow[v] * c);
        ssum0 += s;
        const float qm = (v == draft) ? INF : qrow[v];
        if (s * bq > bs * qm) { bs = s; bq = qm; bi = v; }
    }

    __shared__ float sh_sum[TPB];
    __shared__ float sh_s[TPB];
    __shared__ float sh_q[TPB];
    __shared__ int   sh_i[TPB];
    sh_sum[tid] = ssum0 + ssum1;
    sh_s[tid] = bs; sh_q[tid] = bq; sh_i[tid] = bi;
    __syncthreads();

    #pragma unroll
    for (int off = TPB / 2; off > 0; off >>= 1) {
        if (tid < off) {
            sh_sum[tid] += sh_sum[tid + off];
            const float os = sh_s[tid + off];
            const float oq = sh_q[tid + off];
            const int   oi = sh_i[tid + off];
            const float x1 = os * sh_q[tid];       // other vs mine, cross-multiplied
            const float x2 = sh_s[tid] * oq;
            // strict win, or exact tie -> lowest index (matches jnp.argmax)
            if (x1 > x2 || (x1 == x2 && oi < sh_i[tid])) {
                sh_s[tid] = os; sh_q[tid] = oq; sh_i[tid] = oi;
            }
        }
        __syncthreads();
    }

    if (tid == 0) {
        if (is_bonus) {
            g_bonus[b] = sh_i[0];
        } else {
            const float sd = ex2(lrow[draft] * c);   // one extra load, L2-resident
            const float p  = sd / sh_sum[0];
            g_accept[row]    = (p >= u[row]) ? 1 : 0;
            g_recovered[row] = sh_i[0];
        }
    }
}

// Sequential early-exit semantics per batch row. Output dtype is FLOAT32
// (confirmed R12: int32 stores of -1 read back as NaN).
__global__ void finalize_kernel(const int* __restrict__ draft_ids,
                                float* __restrict__ out, int B, int K)
{
    const int b = blockIdx.x * blockDim.x + threadIdx.x;
    if (b >= B) return;

    int r = K;
    for (int k = 0; k < K; k++) {
        if (r == K && !g_accept[b * K + k]) r = k;
    }

    for (int k = 0; k < K; k++) {
        int val = PLACEHOLDER_TOKEN_ID;
        if (k < r)       val = draft_ids[b * K + k];
        else if (k == r) val = g_recovered[b * K + k];
        out[b * (K + 1) + k] = (float)val;
    }
    out[b * (K + 1) + K] = (float)((r == K) ? g_bonus[b] : PLACEHOLDER_TOKEN_ID);
}

extern "C" void kernel_launch(void* const* d_in, const int* in_sizes, int n_in,
                              void* d_out, int out_size)
{
    // Layout-agnostic identification by size structure.
    // Sizes {T, (T+B)*V, B, T, B*V, B*V}, B < T < B*V < (T+B)*V:
    //   min -> temperatures; max -> logits;
    //   dup small pair -> draft_token_ids then u (original order);
    //   dup large pair -> q then q_bonus (original order).
    int li = 0, ti = 0;
    for (int i = 1; i < n_in; i++) {
        if (in_sizes[i] > in_sizes[li]) li = i;
        if (in_sizes[i] < in_sizes[ti]) ti = i;
    }
    int rest[4]; int nr = 0;
    for (int i = 0; i < n_in; i++) {
        if (i != li && i != ti) rest[nr++] = i;
    }
    for (int a = 0; a < 3; a++) {
        for (int cc = 0; cc < 3 - a; cc++) {
            if (in_sizes[rest[cc]] > in_sizes[rest[cc + 1]]) {
                int t = rest[cc]; rest[cc] = rest[cc + 1]; rest[cc + 1] = t;
            }
        }
    }
    const int di  = rest[0];
    const int ui  = rest[1];
    const int qi  = rest[2];
    const int qbi = rest[3];

    const int*   draft   = (const int*)  d_in[di];
    const float* logits  = (const float*)d_in[li];
    const float* temps   = (const float*)d_in[ti];
    const float* u       = (const float*)d_in[ui];
    const float* q       = (const float*)d_in[qi];
    const float* q_bonus = (const float*)d_in[qbi];

    const int B = in_sizes[ti];
    const int T = in_sizes[di];
    const int K = T / B;
    const int V = in_sizes[qi] / B;

    row_kernel<<<T + B, TPB>>>(draft, logits, temps, q, q_bonus, u, B, K, V);

    const int fb = 256;
    finalize_kernel<<<(B + fb - 1) / fb, fb>>>(draft, (float*)d_out, B, K);
}